// round 13
// baseline (speedup 1.0000x reference)
#include <cuda_runtime.h>
#include <cuda_bf16.h>
#include <math.h>
#include <stdint.h>

#define BB 2
#define LL 512
#define HH 768
#define EE 512
#define RR 32768
#define HD2 384
#define BE (BB*EE)
#define NREL (BB*RR)
#define NPART 256

typedef __nv_bfloat16 bf16;

// ---------------- static scratch ---------------------------------------------
__device__ __align__(16) bf16 g_repr_hi[BE*HH],   g_repr_lo[BE*HH];
__device__ __align__(16) bf16 g_w1h_hi[HH*HH],    g_w1h_lo[HH*HH];
__device__ __align__(16) bf16 g_w1t_hi[HH*HH],    g_w1t_lo[HH*HH];
__device__ __align__(16) bf16 g_w2h_hi[HD2*HH],   g_w2h_lo[HD2*HH];
__device__ __align__(16) bf16 g_w2t_hi[HD2*HH],   g_w2t_lo[HD2*HH];
__device__ __align__(16) bf16 g_bw_hi[2*HD2*HD2], g_bw_lo[2*HD2*HD2];
__device__ __align__(16) bf16 g_hidh_hi[BE*HH],   g_hidh_lo[BE*HH];
__device__ __align__(16) bf16 g_hidt_hi[BE*HH],   g_hidt_lo[BE*HH];
__device__ __align__(16) bf16 g_tls_hi[BE*HD2],   g_tls_lo[BE*HD2];
__device__ __align__(16) bf16 g_hds_hi[BE*HD2],   g_hds_lo[BE*HD2];
__device__ __align__(16) bf16 g_u_hi[BE*2*HD2],   g_u_lo[BE*2*HD2];
__device__ __align__(16) float g_labh[3*HH];
__device__ __align__(16) float g_labt[3*HH];
__device__ __align__(16) float g_heads[BE*HD2];
__device__ __align__(16) float g_tails[BE*HD2];
__device__ __align__(16) float g_P[BB*EE*EE*2];
__device__ __align__(16) float g_lin4[BE*4];
__device__                float g_partial[NPART];
__device__                unsigned g_cnt = 0;

__device__ __forceinline__ void split2(float v, bf16& h, bf16& l) {
    h = __float2bfloat16(v);
    l = __float2bfloat16(v - __bfloat162float(h));
}

// ---------------- unified prologue: gather + labtab + weight prep --------------
struct PrepJob { const float* src; bf16* dhi; bf16* dlo; int rows, cols, direct; };

#define PREP_REPR   1024
#define PREP_LAB    18
#define PREP_WBLK   1152          // 24 x 48 per job
#define PREP_TOTAL  (PREP_REPR + PREP_LAB + 5 * PREP_WBLK)

__global__ void prep_all(const float* __restrict__ hidden,
                         const int*   __restrict__ ent_start,
                         const float* __restrict__ emb,
                         const float* __restrict__ hW1, const float* __restrict__ hb1,
                         const float* __restrict__ tW1, const float* __restrict__ tb1,
                         PrepJob j0, PrepJob j1, PrepJob j2, PrepJob j3, PrepJob j4) {
    int blk = blockIdx.x;
    int tid = threadIdx.x;
    if (blk < PREP_REPR) {                    // gather+split token hidden
        int eg = blk;
        int b  = eg / EE;
        int idx = __ldg(&ent_start[eg]);
        const float* tok = hidden + (size_t)(b * LL + idx) * HH;
        size_t base = (size_t)eg * HH;
        for (int i = tid; i < HH; i += 256) {
            bf16 h, l;
            split2(tok[i], h, l);
            g_repr_hi[base + i] = h;
            g_repr_lo[base + i] = l;
        }
        return;
    }
    if (blk < PREP_REPR + PREP_LAB) {         // label tables (exact fp32)
        int idx = blk - PREP_REPR;
        int which = idx / 9;
        int r = idx % 9;
        int l = r / 3, cb = r % 3;
        const float* W1 = which ? tW1 : hW1;
        const float* b1 = which ? tb1 : hb1;
        float* tab = which ? g_labt : g_labh;
        int c = cb * 256 + tid;
        float acc = b1[c];
        const float* e = emb + (size_t)l * HH;
        for (int k = 0; k < HH; k++)
            acc += e[k] * W1[(size_t)(HH + k) * HH + c];
        tab[l * HH + c] = acc;
        return;
    }
    // weight transpose + split
    int idx = blk - PREP_REPR - PREP_LAB;
    int z = idx / PREP_WBLK;
    int rem = idx % PREP_WBLK;
    int bx = rem % 24, by = rem / 24;
    PrepJob j = (z == 0) ? j0 : (z == 1) ? j1 : (z == 2) ? j2 : (z == 3) ? j3 : j4;
    __shared__ float tile[32][33];
    int tx = tid & 31, ty = tid >> 5;         // 32 x 8
    int x = bx * 32 + tx;
    if (j.direct) {
        for (int k = 0; k < 4; k++) {
            int r = by * 32 + ty + k * 8;
            if (r < j.rows && x < j.cols) {
                bf16 h, l; split2(j.src[(size_t)r * j.cols + x], h, l);
                j.dhi[(size_t)r * j.cols + x] = h;
                j.dlo[(size_t)r * j.cols + x] = l;
            }
        }
        return;
    }
    for (int k = 0; k < 4; k++) {
        int r = by * 32 + ty + k * 8;
        if (r < j.rows && x < j.cols) tile[ty + k * 8][tx] = j.src[(size_t)r * j.cols + x];
    }
    __syncthreads();
    int c = by * 32 + tx;
    for (int k = 0; k < 4; k++) {
        int r = bx * 32 + ty + k * 8;
        if (r < j.cols && c < j.rows) {
            bf16 h, l; split2(tile[tx][ty + k * 8], h, l);
            j.dhi[(size_t)r * j.rows + c] = h;
            j.dlo[(size_t)r * j.rows + c] = l;
        }
    }
}

// ------ GEMM: BM64 x BN64, 8 warps (split-K: 2 groups x 4 warps), 3-stage ------
// Warps 0-3 compute k16 substep 0, warps 4-7 substep 1; epilogue reduces.
// A [M][K], B [N][K] row-major bf16 (hi/lo planes). C = (Ahi+Alo)(Bhi+Blo)^T.
struct GArgs {
    const bf16 *Ahi, *Alo, *Bhi, *Blo;
    const float* bias;        // per-column bias (or null)
    const float* rowTab;      // per-row label table [3][N] (or null)
    const int*   rowLab;      // label per M-row
    float* outF;
    bf16 *Chi, *Clo;
};

#define CPA16(saddr, gptr) \
    asm volatile("cp.async.cg.shared.global [%0], [%1], 16;\n" :: "r"(saddr), "l"(gptr))
#define CP_COMMIT() asm volatile("cp.async.commit_group;\n")
#define CP_WAIT2()  asm volatile("cp.async.wait_group 2;\n")

#define MMA_BF16(c, a, b) asm volatile( \
    "mma.sync.aligned.m16n8k16.row.col.f32.bf16.bf16.f32 " \
    "{%0,%1,%2,%3}, {%4,%5,%6,%7}, {%8,%9}, {%0,%1,%2,%3};\n" \
    : "+f"(c[0]), "+f"(c[1]), "+f"(c[2]), "+f"(c[3]) \
    : "r"(a[0]), "r"(a[1]), "r"(a[2]), "r"(a[3]), "r"(b[0]), "r"(b[1]))

#define LDSM4(r0, r1, r2, r3, addr) asm volatile( \
    "ldmatrix.sync.aligned.m8n8.x4.shared.b16 {%0,%1,%2,%3}, [%4];\n" \
    : "=r"(r0), "=r"(r1), "=r"(r2), "=r"(r3) : "r"(addr))

// stage layout (bytes): Ahi[64x40bf16] @0, Alo @5120, Bhi @10240, Blo @15360
#define STG_BYTES 20480
#define NSTAGE 3

template<bool RELU>
__global__ __launch_bounds__(256)
void mma_gemm(GArgs arg0, GArgs arg1, int M, int N, int K) {
    GArgs ar = (blockIdx.z == 1) ? arg1 : arg0;
    extern __shared__ __align__(16) bf16 sm[];

    int tid  = threadIdx.x;
    int lane = tid & 31, warp = tid >> 5;          // 8 warps
    int grp  = warp >> 2;                          // split-K group (k16 substep)
    int w4   = warp & 3;
    int wm = w4 >> 1, wn = w4 & 1;                 // 2 x 2, each 32x32 tile
    int g  = lane >> 2, c2 = (lane & 3) * 2;
    int m0 = blockIdx.y * 64, n0 = blockIdx.x * 64;

    float CH[2][4][4] = {}, CX[2][4][4] = {};      // [mt][nt][quad]

    uint32_t smBase = (uint32_t)__cvta_generic_to_shared(sm);

    const bf16* srcs[4] = {
        ar.Ahi + (size_t)m0 * K, ar.Alo + (size_t)m0 * K,
        ar.Bhi + (size_t)n0 * K, ar.Blo + (size_t)n0 * K };

    // ldmatrix addresses (within-stage byte offsets); this group's k16 substep
    uint32_t kOff = (uint32_t)grp * 32;            // 16 bf16 = 32 bytes
    uint32_t aRow = wm * 32 + (lane & 15);
    uint32_t aOffHi = smBase + aRow * 80 + ((lane >> 4) & 1) * 16 + kOff;
    uint32_t bRow0 = wn * 32 + (lane & 7) + ((lane >> 4) & 1) * 8;
    uint32_t bOffHi = smBase + 10240 + bRow0 * 80 + ((lane >> 3) & 1) * 16 + kOff;

    int KT = K >> 5;

    // staging: 1024 x 16B chunks per stage, 4 per thread (256 threads)
#define ISSUE(s, kt) do {                                            \
        int kbase = (kt) * 32;                                       \
        uint32_t sb = smBase + (s) * STG_BYTES;                      \
        _Pragma("unroll")                                            \
        for (int i = 0; i < 4; i++) {                                \
            int id = i * 256 + tid;                                  \
            int plane = id >> 8;                                     \
            int loc = id & 255;                                      \
            int row = loc >> 2, ck = loc & 3;                        \
            const bf16* gp = srcs[plane] + (size_t)row * K + kbase + ck * 8; \
            CPA16(sb + plane * 5120 + row * 80 + ck * 16, gp);       \
        }                                                            \
        CP_COMMIT();                                                 \
    } while (0)

    ISSUE(0, 0);
    if (1 < KT) ISSUE(1, 1); else CP_COMMIT();

    for (int kt = 0; kt < KT; kt++) {
        if (kt + 2 < KT) ISSUE((kt + 2) % NSTAGE, kt + 2); else CP_COMMIT();
        CP_WAIT2();                     // oldest (stage kt) complete
        __syncthreads();

        uint32_t kb = (uint32_t)(kt % NSTAGE) * STG_BYTES;
        uint32_t aH[2][4], aL[2][4], bH[4][2], bL[4][2];
        LDSM4(aH[0][0], aH[0][1], aH[0][2], aH[0][3], aOffHi + kb);
        LDSM4(aH[1][0], aH[1][1], aH[1][2], aH[1][3], aOffHi + kb + 16 * 80);
        LDSM4(aL[0][0], aL[0][1], aL[0][2], aL[0][3], aOffHi + kb + 5120);
        LDSM4(aL[1][0], aL[1][1], aL[1][2], aL[1][3], aOffHi + kb + 5120 + 16 * 80);
        LDSM4(bH[0][0], bH[0][1], bH[1][0], bH[1][1], bOffHi + kb);
        LDSM4(bH[2][0], bH[2][1], bH[3][0], bH[3][1], bOffHi + kb + 16 * 80);
        LDSM4(bL[0][0], bL[0][1], bL[1][0], bL[1][1], bOffHi + kb + 5120);
        LDSM4(bL[2][0], bL[2][1], bL[3][0], bL[3][1], bOffHi + kb + 5120 + 16 * 80);
#pragma unroll
        for (int mt = 0; mt < 2; mt++)
#pragma unroll
            for (int nt = 0; nt < 4; nt++) {
                MMA_BF16(CH[mt][nt], aH[mt], bH[nt]);
                MMA_BF16(CX[mt][nt], aH[mt], bL[nt]);
                MMA_BF16(CX[mt][nt], aL[mt], bH[nt]);
            }
        __syncthreads();                // readers done before stage reuse
    }
#undef ISSUE

    // ---- split-K reduction: group 1 dumps partials to smem, group 0 adds ----
    float* red = (float*)sm;            // stages no longer needed (16 KB used)
    if (grp == 1) {
        float* dst = red + (size_t)w4 * 1024;
#pragma unroll
        for (int mt = 0; mt < 2; mt++)
#pragma unroll
            for (int nt = 0; nt < 4; nt++)
#pragma unroll
                for (int q = 0; q < 4; q++)
                    dst[(mt * 16 + nt * 4 + q) * 32 + lane] =
                        CH[mt][nt][q] + CX[mt][nt][q];
    }
    __syncthreads();
    if (grp != 0) return;

    const float* src = red + (size_t)w4 * 1024;
    // epilogue: warp owns rows m0+wm*32..+31, cols n0+wn*32..+31
#pragma unroll
    for (int mt = 0; mt < 2; mt++) {
        int rowb = m0 + wm * 32 + mt * 16 + g;
#pragma unroll
        for (int half = 0; half < 2; half++) {
            int rr = rowb + half * 8;
            int lb = ar.rowTab ? __ldg(&ar.rowLab[rr]) : 0;
#pragma unroll
            for (int nt = 0; nt < 4; nt++) {
                int col = n0 + wn * 32 + nt * 8 + c2;
                int q0 = half * 2 + 0, q1 = half * 2 + 1;
                float v0 = CH[mt][nt][q0] + CX[mt][nt][q0]
                         + src[(mt * 16 + nt * 4 + q0) * 32 + lane];
                float v1 = CH[mt][nt][q1] + CX[mt][nt][q1]
                         + src[(mt * 16 + nt * 4 + q1) * 32 + lane];
                if (ar.rowTab) {
                    const float* t = ar.rowTab + (size_t)lb * N + col;
                    v0 += __ldg(t); v1 += __ldg(t + 1);
                } else if (ar.bias) {
                    v0 += __ldg(&ar.bias[col]); v1 += __ldg(&ar.bias[col + 1]);
                }
                if (RELU) { v0 = fmaxf(v0, 0.0f); v1 = fmaxf(v1, 0.0f); }
                size_t o = (size_t)rr * N + col;
                if (ar.outF) *(float2*)(ar.outF + o) = make_float2(v0, v1);
                if (ar.Chi) {
                    bf16 h0, l0, h1, l1;
                    split2(v0, h0, l0); split2(v1, h1, l1);
                    *(__nv_bfloat162*)(ar.Chi + o) = __halves2bfloat162(h0, h1);
                    *(__nv_bfloat162*)(ar.Clo + o) = __halves2bfloat162(l0, l1);
                }
            }
        }
    }
}

// ---------------- per-entity linear-term dots ----------------------------------
__global__ void lin_kernel(const float* __restrict__ lin_W) {
    int gw   = (blockIdx.x * blockDim.x + threadIdx.x) >> 5;
    int lane = threadIdx.x & 31;
    if (gw >= BE) return;
    const float* h = g_heads + (size_t)gw * HD2;
    const float* t = g_tails + (size_t)gw * HD2;
    float a0 = 0, a1 = 0, a2 = 0, a3 = 0;
    for (int d = lane; d < HD2; d += 32) {
        float hw = h[d], tw = t[d];
        a0 += hw * lin_W[d * 2 + 0];
        a1 += hw * lin_W[d * 2 + 1];
        a2 += tw * lin_W[(HD2 + d) * 2 + 0];
        a3 += tw * lin_W[(HD2 + d) * 2 + 1];
    }
#pragma unroll
    for (int o = 16; o > 0; o >>= 1) {
        a0 += __shfl_down_sync(~0u, a0, o);
        a1 += __shfl_down_sync(~0u, a1, o);
        a2 += __shfl_down_sync(~0u, a2, o);
        a3 += __shfl_down_sync(~0u, a3, o);
    }
    if (lane == 0) {
        float* p = g_lin4 + (size_t)gw * 4;
        p[0] = a0; p[1] = a1; p[2] = a2; p[3] = a3;
    }
}

// ------ per-relation gather + logits + CE + fused deterministic reduction ------
__global__ void rel_gather(const int* __restrict__ rel_head,
                           const int* __restrict__ rel_tail,
                           const int* __restrict__ rel_label,
                           const float* __restrict__ lin_b,
                           float* __restrict__ logits_out,
                           float* __restrict__ out, int write_loss) {
    __shared__ float sh[256];
    __shared__ int is_last;
    int r = blockIdx.x * 256 + threadIdx.x;
    int b = r >> 15;
    int he = rel_head[r], te = rel_tail[r], lab = rel_label[r];
    float2 lhv = *(const float2*)(g_lin4 + (size_t)(b * EE + he) * 4);
    float2 ltv = *(const float2*)(g_lin4 + (size_t)(b * EE + te) * 4 + 2);
    float2 p = *(const float2*)(g_P + ((size_t)b * EE + he) * (EE * 2) + te * 2);
    float s0 = p.x + lhv.x + ltv.x + lin_b[0];
    float s1 = p.y + lhv.y + ltv.y + lin_b[1];
    logits_out[(size_t)r * 2 + 0] = s0;     // scalar stores: 4B-aligned dest
    logits_out[(size_t)r * 2 + 1] = s1;
    float m   = fmaxf(s0, s1);
    float lse = m + logf(expf(s0 - m) + expf(s1 - m));
    sh[threadIdx.x] = lse - (lab ? s1 : s0);
    __syncthreads();
    for (int st = 128; st > 0; st >>= 1) {
        if (threadIdx.x < st) sh[threadIdx.x] += sh[threadIdx.x + st];
        __syncthreads();
    }
    if (threadIdx.x == 0) {
        g_partial[blockIdx.x] = sh[0];
        __threadfence();
        unsigned old = atomicInc(&g_cnt, NPART - 1);   // wraps to 0 on last block
        is_last = (old == NPART - 1);
    }
    __syncthreads();
    if (is_last) {
        float acc = g_partial[threadIdx.x];            // NPART == blockDim == 256
        sh[threadIdx.x] = acc;
        __syncthreads();
        for (int st = 128; st > 0; st >>= 1) {
            if (threadIdx.x < st) sh[threadIdx.x] += sh[threadIdx.x + st];
            __syncthreads();
        }
        if (threadIdx.x == 0 && write_loss) out[0] = sh[0] / (float)RR;
    }
}

// ---------------- launcher ------------------------------------------------------
#define SYM(p, s) do { if (!(p)) cudaGetSymbolAddress((void**)&(p), s); } while (0)
#define GEMM_SMEM (NSTAGE * STG_BYTES)

extern "C" void kernel_launch(void* const* d_in, const int* in_sizes, int n_in,
                              void* d_out, int out_size) {
    const float* hidden     = (const float*)d_in[0];
    const int*   ent_start  = (const int*)  d_in[1];
    const int*   ent_label  = (const int*)  d_in[2];
    const int*   rel_head   = (const int*)  d_in[3];
    const int*   rel_tail   = (const int*)  d_in[4];
    const int*   rel_label  = (const int*)  d_in[5];
    const float* entity_emb = (const float*)d_in[6];
    const float* head_W1 = (const float*)d_in[7];
    const float* head_b1 = (const float*)d_in[8];
    const float* head_W2 = (const float*)d_in[9];
    const float* head_b2 = (const float*)d_in[10];
    const float* tail_W1 = (const float*)d_in[11];
    const float* tail_b1 = (const float*)d_in[12];
    const float* tail_W2 = (const float*)d_in[13];
    const float* tail_b2 = (const float*)d_in[14];
    const float* bil_W   = (const float*)d_in[15];
    const float* lin_W   = (const float*)d_in[16];
    const float* lin_b   = (const float*)d_in[17];
    float* out = (float*)d_out;

    static bf16 *p_repr_hi = nullptr, *p_repr_lo, *p_w1h_hi, *p_w1h_lo,
                *p_w1t_hi, *p_w1t_lo, *p_w2h_hi, *p_w2h_lo, *p_w2t_hi, *p_w2t_lo,
                *p_bw_hi, *p_bw_lo, *p_hidh_hi, *p_hidh_lo, *p_hidt_hi, *p_hidt_lo,
                *p_tls_hi, *p_tls_lo, *p_hds_hi, *p_hds_lo, *p_u_hi, *p_u_lo;
    static float *p_heads = nullptr, *p_tails, *p_P, *p_labh, *p_labt;
    if (!p_repr_hi) {
        SYM(p_repr_hi, g_repr_hi); SYM(p_repr_lo, g_repr_lo);
        SYM(p_w1h_hi, g_w1h_hi);   SYM(p_w1h_lo, g_w1h_lo);
        SYM(p_w1t_hi, g_w1t_hi);   SYM(p_w1t_lo, g_w1t_lo);
        SYM(p_w2h_hi, g_w2h_hi);   SYM(p_w2h_lo, g_w2h_lo);
        SYM(p_w2t_hi, g_w2t_hi);   SYM(p_w2t_lo, g_w2t_lo);
        SYM(p_bw_hi, g_bw_hi);     SYM(p_bw_lo, g_bw_lo);
        SYM(p_hidh_hi, g_hidh_hi); SYM(p_hidh_lo, g_hidh_lo);
        SYM(p_hidt_hi, g_hidt_hi); SYM(p_hidt_lo, g_hidt_lo);
        SYM(p_tls_hi, g_tls_hi);   SYM(p_tls_lo, g_tls_lo);
        SYM(p_hds_hi, g_hds_hi);   SYM(p_hds_lo, g_hds_lo);
        SYM(p_u_hi, g_u_hi);       SYM(p_u_lo, g_u_lo);
        SYM(p_heads, g_heads);     SYM(p_tails, g_tails);
        SYM(p_P, g_P);
        SYM(p_labh, g_labh);       SYM(p_labt, g_labt);
        cudaFuncSetAttribute(mma_gemm<true>,
            cudaFuncAttributeMaxDynamicSharedMemorySize, GEMM_SMEM);
        cudaFuncSetAttribute(mma_gemm<false>,
            cudaFuncAttributeMaxDynamicSharedMemorySize, GEMM_SMEM);
    }

    int loff = out_size - 2 * NREL;
    if (loff < 0) loff = 0;
    float* logits_out = out + loff;

    PrepJob j0 = { head_W1, p_w1h_hi, p_w1h_lo, HH, HH, 0 };
    PrepJob j1 = { tail_W1, p_w1t_hi, p_w1t_lo, HH, HH, 0 };
    PrepJob j2 = { head_W2, p_w2h_hi, p_w2h_lo, HH, HD2, 0 };
    PrepJob j3 = { tail_W2, p_w2t_hi, p_w2t_lo, HH, HD2, 0 };
    PrepJob j4 = { bil_W,   p_bw_hi,  p_bw_lo,  2 * HD2, HD2, 1 };
    prep_all<<<PREP_TOTAL, 256>>>(hidden, ent_start, entity_emb,
        head_W1, head_b1, tail_W1, tail_b1, j0, j1, j2, j3, j4);

    // L1: tok[1024,768] x W1_top^T[768,768] + labTab -> hid (bf16 split), ReLU
    {
        GArgs a0 = { p_repr_hi, p_repr_lo, p_w1h_hi, p_w1h_lo, nullptr,
                     p_labh, ent_label, nullptr, p_hidh_hi, p_hidh_lo };
        GArgs a1 = { p_repr_hi, p_repr_lo, p_w1t_hi, p_w1t_lo, nullptr,
                     p_labt, ent_label, nullptr, p_hidt_hi, p_hidt_lo };
        mma_gemm<true><<<dim3(HH / 64, BE / 64, 2), 256, GEMM_SMEM>>>(
            a0, a1, BE, HH, HH);
    }
    // L2: [1024,768] x [384,768]^T -> heads/tails (f32 + bf16 split), bias+ReLU
    {
        GArgs a0 = { p_hidh_hi, p_hidh_lo, p_w2h_hi, p_w2h_lo, head_b2,
                     nullptr, nullptr, p_heads, p_hds_hi, p_hds_lo };
        GArgs a1 = { p_hidt_hi, p_hidt_lo, p_w2t_hi, p_w2t_lo, tail_b2,
                     nullptr, nullptr, p_tails, p_tls_hi, p_tls_lo };
        mma_gemm<true><<<dim3(HD2 / 64, BE / 64, 2), 256, GEMM_SMEM>>>(
            a0, a1, BE, HD2, HH);
    }
    // U: [1024,384] x bilW[768,384]^T -> u (bf16 split)
    {
        GArgs a0 = { p_tls_hi, p_tls_lo, p_bw_hi, p_bw_lo, nullptr,
                     nullptr, nullptr, nullptr, p_u_hi, p_u_lo };
        mma_gemm<false><<<dim3(2 * HD2 / 64, BE / 64, 1), 256, GEMM_SMEM>>>(
            a0, a0, BE, 2 * HD2, HD2);
    }
    // P: per-batch all-pairs: heads_b [512,384] x u_b [1024,384]^T
    {
        GArgs a0 = { p_hds_hi, p_hds_lo, p_u_hi, p_u_lo, nullptr,
                     nullptr, nullptr, p_P, nullptr, nullptr };
        GArgs a1 = { p_hds_hi + (size_t)EE * HD2, p_hds_lo + (size_t)EE * HD2,
                     p_u_hi + (size_t)EE * 2 * HD2, p_u_lo + (size_t)EE * 2 * HD2,
                     nullptr, nullptr, nullptr,
                     p_P + (size_t)EE * EE * 2, nullptr, nullptr };
        mma_gemm<false><<<dim3(EE * 2 / 64, EE / 64, 2), 256, GEMM_SMEM>>>(
            a0, a1, EE, EE * 2, HD2);
    }

    lin_kernel<<<BE * 32 / 256, 256>>>(lin_W);
    rel_gather<<<NPART, 256>>>(rel_head, rel_tail, rel_label, lin_b,
                               logits_out, out, loff > 0 ? 1 : 0);
}

// round 14
// speedup vs baseline: 1.1866x; 1.1866x over previous
#include <cuda_runtime.h>
#include <cuda_bf16.h>
#include <math.h>
#include <stdint.h>

#define BB 2
#define LL 512
#define HH 768
#define EE 512
#define RR 32768
#define HD2 384
#define BE (BB*EE)
#define NREL (BB*RR)
#define NPART 256

typedef __nv_bfloat16 bf16;

// ---------------- static scratch ---------------------------------------------
__device__ __align__(16) bf16 g_repr_hi[BE*HH],   g_repr_lo[BE*HH];
__device__ __align__(16) bf16 g_w1h_hi[HH*HH],    g_w1h_lo[HH*HH];
__device__ __align__(16) bf16 g_w1t_hi[HH*HH],    g_w1t_lo[HH*HH];
__device__ __align__(16) bf16 g_w2h_hi[HD2*HH],   g_w2h_lo[HD2*HH];
__device__ __align__(16) bf16 g_w2t_hi[HD2*HH],   g_w2t_lo[HD2*HH];
__device__ __align__(16) bf16 g_bw_hi[2*HD2*HD2], g_bw_lo[2*HD2*HD2];
__device__ __align__(16) bf16 g_hidh_hi[BE*HH],   g_hidh_lo[BE*HH];
__device__ __align__(16) bf16 g_hidt_hi[BE*HH],   g_hidt_lo[BE*HH];
__device__ __align__(16) bf16 g_tls_hi[BE*HD2],   g_tls_lo[BE*HD2];
__device__ __align__(16) bf16 g_hds_hi[BE*HD2],   g_hds_lo[BE*HD2];
__device__ __align__(16) bf16 g_u_hi[BE*2*HD2],   g_u_lo[BE*2*HD2];
__device__ __align__(16) float g_labh[3*HH];
__device__ __align__(16) float g_labt[3*HH];
__device__ __align__(16) float g_heads[BE*HD2];
__device__ __align__(16) float g_tails[BE*HD2];
__device__ __align__(16) float g_P[BB*EE*EE*2];
__device__ __align__(16) float g_lin4[BE*4];
__device__                float g_partial[NPART];
__device__                unsigned g_cnt = 0;

__device__ __forceinline__ void split2(float v, bf16& h, bf16& l) {
    h = __float2bfloat16(v);
    l = __float2bfloat16(v - __bfloat162float(h));
}

// ---------------- unified prologue: gather + labtab + weight prep --------------
struct PrepJob { const float* src; bf16* dhi; bf16* dlo; int rows, cols, direct; };

#define PREP_REPR   1024
#define PREP_LAB    18
#define PREP_WBLK   1152          // 24 x 48 per job
#define PREP_TOTAL  (PREP_REPR + PREP_LAB + 5 * PREP_WBLK)

__global__ void prep_all(const float* __restrict__ hidden,
                         const int*   __restrict__ ent_start,
                         const float* __restrict__ emb,
                         const float* __restrict__ hW1, const float* __restrict__ hb1,
                         const float* __restrict__ tW1, const float* __restrict__ tb1,
                         PrepJob j0, PrepJob j1, PrepJob j2, PrepJob j3, PrepJob j4) {
    int blk = blockIdx.x;
    int tid = threadIdx.x;
    if (blk < PREP_REPR) {                    // gather+split token hidden
        int eg = blk;
        int b  = eg / EE;
        int idx = __ldg(&ent_start[eg]);
        const float* tok = hidden + (size_t)(b * LL + idx) * HH;
        size_t base = (size_t)eg * HH;
        for (int i = tid; i < HH; i += 256) {
            bf16 h, l;
            split2(tok[i], h, l);
            g_repr_hi[base + i] = h;
            g_repr_lo[base + i] = l;
        }
        return;
    }
    if (blk < PREP_REPR + PREP_LAB) {         // label tables (exact fp32)
        int idx = blk - PREP_REPR;
        int which = idx / 9;
        int r = idx % 9;
        int l = r / 3, cb = r % 3;
        const float* W1 = which ? tW1 : hW1;
        const float* b1 = which ? tb1 : hb1;
        float* tab = which ? g_labt : g_labh;
        int c = cb * 256 + tid;
        float acc = b1[c];
        const float* e = emb + (size_t)l * HH;
        for (int k = 0; k < HH; k++)
            acc += e[k] * W1[(size_t)(HH + k) * HH + c];
        tab[l * HH + c] = acc;
        return;
    }
    // weight transpose + split
    int idx = blk - PREP_REPR - PREP_LAB;
    int z = idx / PREP_WBLK;
    int rem = idx % PREP_WBLK;
    int bx = rem % 24, by = rem / 24;
    PrepJob j = (z == 0) ? j0 : (z == 1) ? j1 : (z == 2) ? j2 : (z == 3) ? j3 : j4;
    __shared__ float tile[32][33];
    int tx = tid & 31, ty = tid >> 5;         // 32 x 8
    int x = bx * 32 + tx;
    if (j.direct) {
        for (int k = 0; k < 4; k++) {
            int r = by * 32 + ty + k * 8;
            if (r < j.rows && x < j.cols) {
                bf16 h, l; split2(j.src[(size_t)r * j.cols + x], h, l);
                j.dhi[(size_t)r * j.cols + x] = h;
                j.dlo[(size_t)r * j.cols + x] = l;
            }
        }
        return;
    }
    for (int k = 0; k < 4; k++) {
        int r = by * 32 + ty + k * 8;
        if (r < j.rows && x < j.cols) tile[ty + k * 8][tx] = j.src[(size_t)r * j.cols + x];
    }
    __syncthreads();
    int c = by * 32 + tx;
    for (int k = 0; k < 4; k++) {
        int r = bx * 32 + ty + k * 8;
        if (r < j.cols && c < j.rows) {
            bf16 h, l; split2(tile[tx][ty + k * 8], h, l);
            j.dhi[(size_t)r * j.rows + c] = h;
            j.dlo[(size_t)r * j.rows + c] = l;
        }
    }
}

// ---------------- GEMM: BM64 x BN64, 4 warps (32x32 warp tile), 3-stage -------
// A [M][K], B [N][K] row-major bf16 (hi/lo planes). C = (Ahi+Alo)(Bhi+Blo)^T.
// linFuse: blockIdx.z==1 slice computes per-entity linear-term dots instead
// (same dependency as the GEMM's A input; overlaps with the GEMM wave).
struct GArgs {
    const bf16 *Ahi, *Alo, *Bhi, *Blo;
    const float* bias;        // per-column bias (or null); lin_W for lin slice
    const float* rowTab;      // per-row label table [3][N] (or null)
    const int*   rowLab;      // label per M-row
    float* outF;
    bf16 *Chi, *Clo;
};

#define CPA16(saddr, gptr) \
    asm volatile("cp.async.cg.shared.global [%0], [%1], 16;\n" :: "r"(saddr), "l"(gptr))
#define CP_COMMIT() asm volatile("cp.async.commit_group;\n")
#define CP_WAIT2()  asm volatile("cp.async.wait_group 2;\n")

#define MMA_BF16(c, a, b) asm volatile( \
    "mma.sync.aligned.m16n8k16.row.col.f32.bf16.bf16.f32 " \
    "{%0,%1,%2,%3}, {%4,%5,%6,%7}, {%8,%9}, {%0,%1,%2,%3};\n" \
    : "+f"(c[0]), "+f"(c[1]), "+f"(c[2]), "+f"(c[3]) \
    : "r"(a[0]), "r"(a[1]), "r"(a[2]), "r"(a[3]), "r"(b[0]), "r"(b[1]))

#define LDSM4(r0, r1, r2, r3, addr) asm volatile( \
    "ldmatrix.sync.aligned.m8n8.x4.shared.b16 {%0,%1,%2,%3}, [%4];\n" \
    : "=r"(r0), "=r"(r1), "=r"(r2), "=r"(r3) : "r"(addr))

// stage layout (bytes): Ahi[64x40bf16] @0, Alo @5120, Bhi @10240, Blo @15360
#define STG_BYTES 20480
#define NSTAGE 3

template<bool RELU>
__global__ __launch_bounds__(128)
void mma_gemm(GArgs arg0, GArgs arg1, int M, int N, int K, int linFuse) {
    // ---- fused lin slice: 4 dots of length 384 per entity, 1 per warp ----
    if (linFuse && blockIdx.z == 1) {
        const float* lin_W = arg1.bias;
        int fb   = blockIdx.y * gridDim.x + blockIdx.x;   // 0 .. 191
        int nblk = gridDim.x * gridDim.y;
        int warp = threadIdx.x >> 5, lane = threadIdx.x & 31;
        const float* vecs = (warp < 2) ? g_heads : g_tails;
        int o    = warp & 1;
        int base = (warp < 2) ? 0 : HD2;
        for (int e = fb; e < BE; e += nblk) {
            const float* v = vecs + (size_t)e * HD2;
            float a = 0.0f;
            for (int d = lane; d < HD2; d += 32)
                a += v[d] * __ldg(&lin_W[(base + d) * 2 + o]);
#pragma unroll
            for (int off = 16; off > 0; off >>= 1)
                a += __shfl_down_sync(~0u, a, off);
            if (lane == 0) g_lin4[(size_t)e * 4 + warp] = a;
        }
        return;
    }

    GArgs ar = (blockIdx.z == 1) ? arg1 : arg0;
    extern __shared__ __align__(16) bf16 sm[];

    int tid  = threadIdx.x;
    int lane = tid & 31, warp = tid >> 5;          // 4 warps
    int wm = warp >> 1, wn = warp & 1;             // 2 x 2, each 32x32 tile
    int g  = lane >> 2, c2 = (lane & 3) * 2;
    int m0 = blockIdx.y * 64, n0 = blockIdx.x * 64;

    float CH[2][4][4] = {}, CX[2][4][4] = {};      // [mt][nt][quad]

    uint32_t smBase = (uint32_t)__cvta_generic_to_shared(sm);

    const bf16* srcs[4] = {
        ar.Ahi + (size_t)m0 * K, ar.Alo + (size_t)m0 * K,
        ar.Bhi + (size_t)n0 * K, ar.Blo + (size_t)n0 * K };

    // ldmatrix addresses (within-stage byte offsets)
    uint32_t aRow = wm * 32 + (lane & 15);
    uint32_t aOffHi = smBase + aRow * 80 + ((lane >> 4) & 1) * 16;
    uint32_t bRow0 = wn * 32 + (lane & 7) + ((lane >> 4) & 1) * 8;
    uint32_t bOffHi = smBase + 10240 + bRow0 * 80 + ((lane >> 3) & 1) * 16;

    int KT = K >> 5;

#define ISSUE(s, kt) do {                                            \
        int kbase = (kt) * 32;                                       \
        uint32_t sb = smBase + (s) * STG_BYTES;                      \
        _Pragma("unroll")                                            \
        for (int i = 0; i < 8; i++) {                                \
            int id = i * 128 + tid;                                  \
            int plane = id >> 8;                                     \
            int loc = id & 255;                                      \
            int row = loc >> 2, ck = loc & 3;                        \
            const bf16* gp = srcs[plane] + (size_t)row * K + kbase + ck * 8; \
            CPA16(sb + plane * 5120 + row * 80 + ck * 16, gp);       \
        }                                                            \
        CP_COMMIT();                                                 \
    } while (0)

    ISSUE(0, 0);
    if (1 < KT) ISSUE(1, 1); else CP_COMMIT();

    for (int kt = 0; kt < KT; kt++) {
        if (kt + 2 < KT) ISSUE((kt + 2) % NSTAGE, kt + 2); else CP_COMMIT();
        CP_WAIT2();                     // oldest (stage kt) complete
        __syncthreads();

        uint32_t stB = (uint32_t)(kt % NSTAGE) * STG_BYTES;
#pragma unroll
        for (int kk = 0; kk < 2; kk++) {
            uint32_t kb = stB + kk * 32;
            uint32_t aH[2][4], aL[2][4], bH[4][2], bL[4][2];
            LDSM4(aH[0][0], aH[0][1], aH[0][2], aH[0][3], aOffHi + kb);
            LDSM4(aH[1][0], aH[1][1], aH[1][2], aH[1][3], aOffHi + kb + 16 * 80);
            LDSM4(aL[0][0], aL[0][1], aL[0][2], aL[0][3], aOffHi + kb + 5120);
            LDSM4(aL[1][0], aL[1][1], aL[1][2], aL[1][3], aOffHi + kb + 5120 + 16 * 80);
            LDSM4(bH[0][0], bH[0][1], bH[1][0], bH[1][1], bOffHi + kb);
            LDSM4(bH[2][0], bH[2][1], bH[3][0], bH[3][1], bOffHi + kb + 16 * 80);
            LDSM4(bL[0][0], bL[0][1], bL[1][0], bL[1][1], bOffHi + kb + 5120);
            LDSM4(bL[2][0], bL[2][1], bL[3][0], bL[3][1], bOffHi + kb + 5120 + 16 * 80);
#pragma unroll
            for (int mt = 0; mt < 2; mt++)
#pragma unroll
                for (int nt = 0; nt < 4; nt++) {
                    MMA_BF16(CH[mt][nt], aH[mt], bH[nt]);
                    MMA_BF16(CX[mt][nt], aH[mt], bL[nt]);
                    MMA_BF16(CX[mt][nt], aL[mt], bH[nt]);
                }
        }
        __syncthreads();                // readers done before stage reuse
    }
#undef ISSUE

    // epilogue: warp owns rows m0+wm*32..+31, cols n0+wn*32..+31
#pragma unroll
    for (int mt = 0; mt < 2; mt++) {
        int rowb = m0 + wm * 32 + mt * 16 + g;
#pragma unroll
        for (int half = 0; half < 2; half++) {
            int rr = rowb + half * 8;
            int lb = ar.rowTab ? __ldg(&ar.rowLab[rr]) : 0;
#pragma unroll
            for (int nt = 0; nt < 4; nt++) {
                int col = n0 + wn * 32 + nt * 8 + c2;
                float v0 = CH[mt][nt][half * 2 + 0] + CX[mt][nt][half * 2 + 0];
                float v1 = CH[mt][nt][half * 2 + 1] + CX[mt][nt][half * 2 + 1];
                if (ar.rowTab) {
                    const float* t = ar.rowTab + (size_t)lb * N + col;
                    v0 += __ldg(t); v1 += __ldg(t + 1);
                } else if (ar.bias) {
                    v0 += __ldg(&ar.bias[col]); v1 += __ldg(&ar.bias[col + 1]);
                }
                if (RELU) { v0 = fmaxf(v0, 0.0f); v1 = fmaxf(v1, 0.0f); }
                size_t o = (size_t)rr * N + col;
                if (ar.outF) *(float2*)(ar.outF + o) = make_float2(v0, v1);
                if (ar.Chi) {
                    bf16 h0, l0, h1, l1;
                    split2(v0, h0, l0); split2(v1, h1, l1);
                    *(__nv_bfloat162*)(ar.Chi + o) = __halves2bfloat162(h0, h1);
                    *(__nv_bfloat162*)(ar.Clo + o) = __halves2bfloat162(l0, l1);
                }
            }
        }
    }
}

// ------ per-relation gather + logits + CE + fused deterministic reduction ------
__global__ void rel_gather(const int* __restrict__ rel_head,
                           const int* __restrict__ rel_tail,
                           const int* __restrict__ rel_label,
                           const float* __restrict__ lin_b,
                           float* __restrict__ logits_out,
                           float* __restrict__ out, int write_loss) {
    __shared__ float sh[256];
    __shared__ int is_last;
    int r = blockIdx.x * 256 + threadIdx.x;
    int b = r >> 15;
    int he = rel_head[r], te = rel_tail[r], lab = rel_label[r];
    float2 lhv = *(const float2*)(g_lin4 + (size_t)(b * EE + he) * 4);
    float2 ltv = *(const float2*)(g_lin4 + (size_t)(b * EE + te) * 4 + 2);
    float2 p = *(const float2*)(g_P + ((size_t)b * EE + he) * (EE * 2) + te * 2);
    float s0 = p.x + lhv.x + ltv.x + lin_b[0];
    float s1 = p.y + lhv.y + ltv.y + lin_b[1];
    logits_out[(size_t)r * 2 + 0] = s0;     // scalar stores: 4B-aligned dest
    logits_out[(size_t)r * 2 + 1] = s1;
    float m   = fmaxf(s0, s1);
    float lse = m + logf(expf(s0 - m) + expf(s1 - m));
    sh[threadIdx.x] = lse - (lab ? s1 : s0);
    __syncthreads();
    for (int st = 128; st > 0; st >>= 1) {
        if (threadIdx.x < st) sh[threadIdx.x] += sh[threadIdx.x + st];
        __syncthreads();
    }
    if (threadIdx.x == 0) {
        g_partial[blockIdx.x] = sh[0];
        __threadfence();
        unsigned old = atomicInc(&g_cnt, NPART - 1);   // wraps to 0 on last block
        is_last = (old == NPART - 1);
    }
    __syncthreads();
    if (is_last) {
        float acc = g_partial[threadIdx.x];            // NPART == blockDim == 256
        sh[threadIdx.x] = acc;
        __syncthreads();
        for (int st = 128; st > 0; st >>= 1) {
            if (threadIdx.x < st) sh[threadIdx.x] += sh[threadIdx.x + st];
            __syncthreads();
        }
        if (threadIdx.x == 0 && write_loss) out[0] = sh[0] / (float)RR;
    }
}

// ---------------- launcher ------------------------------------------------------
#define SYM(p, s) do { if (!(p)) cudaGetSymbolAddress((void**)&(p), s); } while (0)
#define GEMM_SMEM (NSTAGE * STG_BYTES)

extern "C" void kernel_launch(void* const* d_in, const int* in_sizes, int n_in,
                              void* d_out, int out_size) {
    const float* hidden     = (const float*)d_in[0];
    const int*   ent_start  = (const int*)  d_in[1];
    const int*   ent_label  = (const int*)  d_in[2];
    const int*   rel_head   = (const int*)  d_in[3];
    const int*   rel_tail   = (const int*)  d_in[4];
    const int*   rel_label  = (const int*)  d_in[5];
    const float* entity_emb = (const float*)d_in[6];
    const float* head_W1 = (const float*)d_in[7];
    const float* head_b1 = (const float*)d_in[8];
    const float* head_W2 = (const float*)d_in[9];
    const float* head_b2 = (const float*)d_in[10];
    const float* tail_W1 = (const float*)d_in[11];
    const float* tail_b1 = (const float*)d_in[12];
    const float* tail_W2 = (const float*)d_in[13];
    const float* tail_b2 = (const float*)d_in[14];
    const float* bil_W   = (const float*)d_in[15];
    const float* lin_W   = (const float*)d_in[16];
    const float* lin_b   = (const float*)d_in[17];
    float* out = (float*)d_out;

    static bf16 *p_repr_hi = nullptr, *p_repr_lo, *p_w1h_hi, *p_w1h_lo,
                *p_w1t_hi, *p_w1t_lo, *p_w2h_hi, *p_w2h_lo, *p_w2t_hi, *p_w2t_lo,
                *p_bw_hi, *p_bw_lo, *p_hidh_hi, *p_hidh_lo, *p_hidt_hi, *p_hidt_lo,
                *p_tls_hi, *p_tls_lo, *p_hds_hi, *p_hds_lo, *p_u_hi, *p_u_lo;
    static float *p_heads = nullptr, *p_tails, *p_P, *p_labh, *p_labt;
    if (!p_repr_hi) {
        SYM(p_repr_hi, g_repr_hi); SYM(p_repr_lo, g_repr_lo);
        SYM(p_w1h_hi, g_w1h_hi);   SYM(p_w1h_lo, g_w1h_lo);
        SYM(p_w1t_hi, g_w1t_hi);   SYM(p_w1t_lo, g_w1t_lo);
        SYM(p_w2h_hi, g_w2h_hi);   SYM(p_w2h_lo, g_w2h_lo);
        SYM(p_w2t_hi, g_w2t_hi);   SYM(p_w2t_lo, g_w2t_lo);
        SYM(p_bw_hi, g_bw_hi);     SYM(p_bw_lo, g_bw_lo);
        SYM(p_hidh_hi, g_hidh_hi); SYM(p_hidh_lo, g_hidh_lo);
        SYM(p_hidt_hi, g_hidt_hi); SYM(p_hidt_lo, g_hidt_lo);
        SYM(p_tls_hi, g_tls_hi);   SYM(p_tls_lo, g_tls_lo);
        SYM(p_hds_hi, g_hds_hi);   SYM(p_hds_lo, g_hds_lo);
        SYM(p_u_hi, g_u_hi);       SYM(p_u_lo, g_u_lo);
        SYM(p_heads, g_heads);     SYM(p_tails, g_tails);
        SYM(p_P, g_P);
        SYM(p_labh, g_labh);       SYM(p_labt, g_labt);
        cudaFuncSetAttribute(mma_gemm<true>,
            cudaFuncAttributeMaxDynamicSharedMemorySize, GEMM_SMEM);
        cudaFuncSetAttribute(mma_gemm<false>,
            cudaFuncAttributeMaxDynamicSharedMemorySize, GEMM_SMEM);
    }

    int loff = out_size - 2 * NREL;
    if (loff < 0) loff = 0;
    float* logits_out = out + loff;

    PrepJob j0 = { head_W1, p_w1h_hi, p_w1h_lo, HH, HH, 0 };
    PrepJob j1 = { tail_W1, p_w1t_hi, p_w1t_lo, HH, HH, 0 };
    PrepJob j2 = { head_W2, p_w2h_hi, p_w2h_lo, HH, HD2, 0 };
    PrepJob j3 = { tail_W2, p_w2t_hi, p_w2t_lo, HH, HD2, 0 };
    PrepJob j4 = { bil_W,   p_bw_hi,  p_bw_lo,  2 * HD2, HD2, 1 };
    prep_all<<<PREP_TOTAL, 256>>>(hidden, ent_start, entity_emb,
        head_W1, head_b1, tail_W1, tail_b1, j0, j1, j2, j3, j4);

    // L1: tok[1024,768] x W1_top^T[768,768] + labTab -> hid (bf16 split), ReLU
    {
        GArgs a0 = { p_repr_hi, p_repr_lo, p_w1h_hi, p_w1h_lo, nullptr,
                     p_labh, ent_label, nullptr, p_hidh_hi, p_hidh_lo };
        GArgs a1 = { p_repr_hi, p_repr_lo, p_w1t_hi, p_w1t_lo, nullptr,
                     p_labt, ent_label, nullptr, p_hidt_hi, p_hidt_lo };
        mma_gemm<true><<<dim3(HH / 64, BE / 64, 2), 128, GEMM_SMEM>>>(
            a0, a1, BE, HH, HH, 0);
    }
    // L2: [1024,768] x [384,768]^T -> heads/tails (f32 + bf16 split), bias+ReLU
    {
        GArgs a0 = { p_hidh_hi, p_hidh_lo, p_w2h_hi, p_w2h_lo, head_b2,
                     nullptr, nullptr, p_heads, p_hds_hi, p_hds_lo };
        GArgs a1 = { p_hidt_hi, p_hidt_lo, p_w2t_hi, p_w2t_lo, tail_b2,
                     nullptr, nullptr, p_tails, p_tls_hi, p_tls_lo };
        mma_gemm<true><<<dim3(HD2 / 64, BE / 64, 2), 128, GEMM_SMEM>>>(
            a0, a1, BE, HD2, HH, 0);
    }
    // U: [1024,384] x bilW[768,384]^T -> u (bf16 split); z=1 slice = lin dots
    {
        GArgs a0 = { p_tls_hi, p_tls_lo, p_bw_hi, p_bw_lo, nullptr,
                     nullptr, nullptr, nullptr, p_u_hi, p_u_lo };
        GArgs a1 = { nullptr, nullptr, nullptr, nullptr, lin_W,
                     nullptr, nullptr, nullptr, nullptr, nullptr };
        mma_gemm<false><<<dim3(2 * HD2 / 64, BE / 64, 2), 128, GEMM_SMEM>>>(
            a0, a1, BE, 2 * HD2, HD2, 1);
    }
    // P: per-batch all-pairs: heads_b [512,384] x u_b [1024,384]^T
    {
        GArgs a0 = { p_hds_hi, p_hds_lo, p_u_hi, p_u_lo, nullptr,
                     nullptr, nullptr, p_P, nullptr, nullptr };
        GArgs a1 = { p_hds_hi + (size_t)EE * HD2, p_hds_lo + (size_t)EE * HD2,
                     p_u_hi + (size_t)EE * 2 * HD2, p_u_lo + (size_t)EE * 2 * HD2,
                     nullptr, nullptr, nullptr,
                     p_P + (size_t)EE * EE * 2, nullptr, nullptr };
        mma_gemm<false><<<dim3(EE * 2 / 64, EE / 64, 2), 128, GEMM_SMEM>>>(
            a0, a1, EE, EE * 2, HD2, 0);
    }

    rel_gather<<<NPART, 256>>>(rel_head, rel_tail, rel_label, lin_b,
                               logits_out, out, loff > 0 ? 1 : 0);
}